// round 1
// baseline (speedup 1.0000x reference)
#include <cuda_runtime.h>
#include <math_constants.h>

// AutoCorrelation (Autoformer) fused kernel.
// Shapes: q,k,v: (B=32, H=8, L=2048, E=64) fp32.
// corr[b,h,l,d] = sum_e q[b,h,l,(e+d)%64] * k[b,h,l,e]
// top-4 of corr over d, softmax weights, V[e] = sum_i w_i * v[(e+d_i)%64]
// out = concat( V (B,H,L,E), corr transposed to (B,E,H,L) )

#define BB 32
#define HH 8
#define LL 2048
#define EE 64
#define RPB 8          // rows (l values) per block, one warp per row
#define TOPK 4

__global__ __launch_bounds__(256)
void autocorr_kernel(const float* __restrict__ q,
                     const float* __restrict__ k,
                     const float* __restrict__ v,
                     float* __restrict__ outV,
                     float* __restrict__ outC) {
    __shared__ __align__(16) float sq2[RPB][128];   // q doubled: sq2[i] = q[i & 63]
    __shared__ __align__(16) float sk [RPB][64];
    __shared__ __align__(16) float sv2[RPB][128];   // v doubled
    __shared__ float scorr[RPB][72];                // padded stride 72 (bank spread)

    const int tid  = threadIdx.x;
    const int w    = tid >> 5;
    const int lane = tid & 31;

    const long long r0 = (long long)blockIdx.x * RPB;   // first row of block
    const long long r  = r0 + w;                        // this warp's row
    const float* qr = q + r * EE;
    const float* kr = k + r * EE;
    const float* vr = v + r * EE;

    // ---- load row (coalesced), stage doubled copies in shared ----
    float q0 = qr[lane], q1 = qr[lane + 32];
    float k0 = kr[lane], k1 = kr[lane + 32];
    float v0 = vr[lane], v1 = vr[lane + 32];
    sq2[w][lane]      = q0; sq2[w][lane + 32] = q1;
    sq2[w][lane + 64] = q0; sq2[w][lane + 96] = q1;
    sk [w][lane]      = k0; sk [w][lane + 32] = k1;
    sv2[w][lane]      = v0; sv2[w][lane + 32] = v1;
    sv2[w][lane + 64] = v0; sv2[w][lane + 96] = v1;
    __syncwarp();

    // ---- corr: lane computes d0 = 2*lane and d0+1 ----
    const int d0 = lane << 1;
    float c0 = 0.f, c1 = 0.f;
    float2 qa = *(const float2*)&sq2[w][d0];   // (q[d0+e], q[d0+e+1]) at e=0
    #pragma unroll
    for (int e = 0; e < 64; e += 2) {
        float2 ke = *(const float2*)&sk[w][e];              // broadcast
        float2 qb = *(const float2*)&sq2[w][d0 + e + 2];    // next pair
        c0 = fmaf(qa.x, ke.x, c0);
        c0 = fmaf(qa.y, ke.y, c0);
        c1 = fmaf(qa.y, ke.x, c1);
        c1 = fmaf(qb.x, ke.y, c1);
        qa = qb;
    }

    // stage corr for transposed store
    scorr[w][d0]     = c0;
    scorr[w][d0 + 1] = c1;

    // ---- top-4 over 64 corr values (2 per lane), ties -> lowest index ----
    float a0 = c0, a1 = c1;
    float wts[TOPK];
    int   del[TOPK];
    #pragma unroll
    for (int t = 0; t < TOPK; t++) {
        float bv = a0; int bi = d0;
        if (a1 > bv) { bv = a1; bi = d0 + 1; }
        #pragma unroll
        for (int off = 16; off > 0; off >>= 1) {
            float ov = __shfl_xor_sync(0xFFFFFFFFu, bv, off);
            int   oi = __shfl_xor_sync(0xFFFFFFFFu, bi, off);
            if (ov > bv || (ov == bv && oi < bi)) { bv = ov; bi = oi; }
        }
        wts[t] = bv; del[t] = bi;
        if (bi == d0)          a0 = -CUDART_INF_F;
        else if (bi == d0 + 1) a1 = -CUDART_INF_F;
    }

    // ---- softmax over the 4 weights (wts[0] is the max) ----
    float m = wts[0];
    float ex[TOPK];
    float s = 0.f;
    #pragma unroll
    for (int t = 0; t < TOPK; t++) { ex[t] = __expf(wts[t] - m); s += ex[t]; }
    float inv = 1.f / s;

    // ---- aggregate V at e = d0, d0+1 via doubled v ----
    float o0 = 0.f, o1 = 0.f;
    #pragma unroll
    for (int t = 0; t < TOPK; t++) {
        float wt = ex[t] * inv;
        o0 = fmaf(wt, sv2[w][d0 + del[t]],     o0);
        o1 = fmaf(wt, sv2[w][d0 + 1 + del[t]], o1);
    }
    *(float2*)(outV + r * EE + d0) = make_float2(o0, o1);

    // ---- transposed corr store: (B,E,H,L), 8 contiguous l per d ----
    __syncthreads();
    {
        const int b  = (int)(r0 >> 14);          // / (H*L)
        const int h  = (int)((r0 >> 11) & 7);
        const int l0 = (int)(r0 & (LL - 1));
        const int lloc = tid & 7;
        const int d    = tid >> 3;               // 0..31, also do d+32
        const long long lbase = (long long)l0 + lloc;
        const long long bhl = ((long long)b * EE * HH + (long long)h) * LL;
        outC[bhl + (long long)d * (HH * LL) + lbase]        = scorr[lloc][d];
        outC[bhl + (long long)(d + 32) * (HH * LL) + lbase] = scorr[lloc][d + 32];
    }
}

extern "C" void kernel_launch(void* const* d_in, const int* in_sizes, int n_in,
                              void* d_out, int out_size) {
    const float* q = (const float*)d_in[0];
    const float* k = (const float*)d_in[1];
    const float* v = (const float*)d_in[2];
    float* outV = (float*)d_out;
    float* outC = (float*)d_out + (long long)BB * HH * LL * EE;

    const int nblocks = (BB * HH * LL) / RPB;   // 65536
    autocorr_kernel<<<nblocks, 256>>>(q, k, v, outV, outC);
}

// round 2
// speedup vs baseline: 1.3367x; 1.3367x over previous
#include <cuda_runtime.h>
#include <math_constants.h>

// AutoCorrelation (Autoformer): q,k,v (32,8,2048,64) fp32.
// corr[r,d] = sum_e q[r,(e+d)%64]*k[r,e]; top-4 over d, softmax, gather v.
// out = [ V (B,H,L,E) | corr^T (B,E,H,L) ]
// One THREAD per row. k resident in 64 regs; q streamed from smem with
// immediate offsets; 4096 fully-unrolled FFMAs; v doubled in smem for
// immediate-offset gather; all global traffic coalesced via smem staging.

#define RPW 32           // rows per warp (thread = row)
#define STR 131          // smem row stride (odd, coprime 32 -> conflict-free)

__global__ void __launch_bounds__(64, 6)
autocorr_kernel(const float* __restrict__ gq,
                const float* __restrict__ gk,
                const float* __restrict__ gv,
                float* __restrict__ outV,
                float* __restrict__ outC) {
    __shared__ float tile[2][RPW][STR];

    const int w    = threadIdx.x >> 5;
    const int lane = threadIdx.x & 31;
    float (*T)[STR] = tile[w];

    const long long r0  = ((long long)blockIdx.x * 2 + w) * RPW;  // first row of warp
    const long long off = r0 * 64;                                 // element offset

    // ---- stage k (coalesced), then each thread pulls its row into regs ----
    #pragma unroll
    for (int it = 0; it < 64; it++) {
        int f = it * 32 + lane;                 // 32 consecutive floats: same smem row
        T[f >> 6][f & 63] = gk[off + f];        // bank = (3*row + col)%32, conflict-free
    }
    __syncwarp();
    float kr[64];
    #pragma unroll
    for (int j = 0; j < 64; j++) kr[j] = T[lane][j];
    __syncwarp();

    // ---- stage q into the same tile ----
    #pragma unroll
    for (int it = 0; it < 64; it++) {
        int f = it * 32 + lane;
        T[f >> 6][f & 63] = gq[off + f];
    }
    __syncwarp();

    // ---- top-4 state ----
    float w0 = -CUDART_INF_F, w1 = -CUDART_INF_F, w2 = -CUDART_INF_F, w3 = -CUDART_INF_F;
    int   i0 = 0, i1 = 0, i2 = 0, i3 = 0;

    // corr^T addressing: rows of this warp share (b,h); l = l0 + lane
    const int b = (int)(r0 >> 14);
    const int h = ((int)(r0 >> 11)) & 7;
    const int l = ((int)(r0 & 2047)) + lane;
    float* cOut = outC + (long long)b * (64 * 8 * 2048) + (long long)h * 2048 + l;

    // ---- correlation: two passes of 32 accumulators, fully unrolled ----
    #pragma unroll
    for (int pass = 0; pass < 2; pass++) {
        float c[32];
        #pragma unroll
        for (int dd = 0; dd < 32; dd++) c[dd] = 0.f;

        #pragma unroll
        for (int j = 0; j < 64; j++) {
            float qj = T[lane][j];              // LDS [base + imm], 1 phase, reused x32
            #pragma unroll
            for (int dd = 0; dd < 32; dd++) {
                // corr[d] = sum_j q[j] * k[(j-d) mod 64], d = pass*32+dd
                c[dd] = fmaf(qj, kr[(j + 64 - pass * 32 - dd) & 63], c[dd]);
            }
        }

        #pragma unroll
        for (int dd = 0; dd < 32; dd++) {
            const int d = pass * 32 + dd;
            const float v = c[dd];
            // strict-> insertion keeps lowest index on ties (matches lax.top_k)
            if (v > w3) {
                if (v > w2) {
                    if (v > w1) {
                        if (v > w0) { w3=w2;i3=i2; w2=w1;i2=i1; w1=w0;i1=i0; w0=v;i0=d; }
                        else        { w3=w2;i3=i2; w2=w1;i2=i1; w1=v;i1=d; }
                    } else          { w3=w2;i3=i2; w2=v;i2=d; }
                } else              { w3=v;i3=d; }
            }
            cOut[(long long)d * 16384] = v;     // coalesced over lanes (contiguous l)
        }
    }

    // ---- softmax over the 4 weights (w0 is the max) ----
    const float e1 = __expf(w1 - w0), e2 = __expf(w2 - w0), e3 = __expf(w3 - w0);
    const float inv = 1.f / (1.f + e1 + e2 + e3);
    const float t0 = inv, t1 = e1 * inv, t2 = e2 * inv, t3 = e3 * inv;

    // ---- stage v DOUBLED (cols 0..127) for wrap-free immediate-offset gather ----
    #pragma unroll
    for (int it = 0; it < 64; it++) {
        int f = it * 32 + lane;
        float val = gv[off + f];
        T[f >> 6][f & 63]      = val;
        T[f >> 6][(f & 63) + 64] = val;
    }
    __syncwarp();

    // ---- aggregate V[e] = sum_t w_t * v[(e + d_t) % 64]; overwrite lower copy ----
    // Safe in place: col e is only read at iterations e' = e - d_t <= e, and the
    // upper copy (cols 64..127) is never written.
    {
        const float* vr0 = &T[lane][0] + i0;
        const float* vr1 = &T[lane][0] + i1;
        const float* vr2 = &T[lane][0] + i2;
        const float* vr3 = &T[lane][0] + i3;
        float* Vw = &T[lane][0];
        #pragma unroll
        for (int e = 0; e < 64; e++) {
            float s = t0 * vr0[e];
            s = fmaf(t1, vr1[e], s);
            s = fmaf(t2, vr2[e], s);
            s = fmaf(t3, vr3[e], s);
            Vw[e] = s;
        }
    }
    __syncwarp();

    // ---- cooperative coalesced store of V ----
    #pragma unroll
    for (int it = 0; it < 64; it++) {
        int f = it * 32 + lane;
        outV[off + f] = T[f >> 6][f & 63];
    }
}

extern "C" void kernel_launch(void* const* d_in, const int* in_sizes, int n_in,
                              void* d_out, int out_size) {
    const float* q = (const float*)d_in[0];
    const float* k = (const float*)d_in[1];
    const float* v = (const float*)d_in[2];
    float* outV = (float*)d_out;
    float* outC = (float*)d_out + (long long)32 * 8 * 2048 * 64;

    const int rows    = 32 * 8 * 2048;          // 524288
    const int nblocks = rows / (2 * RPW);       // 8192 (64 threads = 2 warps/block)
    autocorr_kernel<<<nblocks, 64>>>(q, k, v, outV, outC);
}